// round 11
// baseline (speedup 1.0000x reference)
#include <cuda_runtime.h>
#include <stdint.h>

#define NBW 120
#define NBH 68
#define NB  8160
#define KWIN 5
#define NOCT 8                    // depth octiles (sort buckets)
#define R 16                      // counters per tile = 8 octiles x 2 replicas
#define SUBCAP 96                 // slots per replica (mean ~27, +13 sigma)
#define CAP (R * SUBCAP)          // 1536 slots per tile

typedef unsigned long long u64;

__device__ int g_counts[NB * R];   // zero-init; reset by k_sort each replay
__device__ int g_offsets[NB];
__device__ int g_total;
__device__ u64 g_keys[(size_t)NB * CAP];  // slot = tile*CAP + rep*SUBCAP + rank

// ---------------------------------------------------------------------------
// Tile range, identical clamping semantics to reference (exact: /16 == *0.0625)
// ---------------------------------------------------------------------------
__device__ __forceinline__ void tile_range(float x, float y, float r,
                                           int& xmin, int& ymin, int& nx, int& ny) {
    const float inv = 0.0625f;
    int x0 = (int)floorf((x - r) * inv);
    int y0 = (int)floorf((y - r) * inv);
    int x1 = (int)floorf((x + r) * inv) + 1;
    int y1 = (int)floorf((y + r) * inv) + 1;
    xmin = min(max(x0, 0), NBW);
    ymin = min(max(y0, 0), NBH);
    int xmax = min(max(x1, 0), NBW);
    int ymax = min(max(y1, 0), NBH);
    nx = min(xmax - xmin, KWIN);
    ny = min(ymax - ymin, KWIN);
}

// Depth octile: equal-mass N(0,1) buckets; larger depth -> lower bucket.
// Function of depth ONLY (ties share a bucket); monotone non-increasing in
// depth -> concatenating sorted buckets in order is a full sort.
__device__ __forceinline__ int depth_bucket(float d) {
    int b = 0;
    b += d < 1.1503494f;
    b += d < 0.6744898f;
    b += d < 0.3186394f;
    b += d < 0.0f;
    b += d < -0.3186394f;
    b += d < -0.6744898f;
    b += d < -1.1503494f;
    return b;
}

// ---------------------------------------------------------------------------
// Pass 1: fused count+scatter. Grid (nb, 5): thread (i, a) handles window
// row a of point i (<=5 cells). Counters split by octile x parity (16/tile).
// ---------------------------------------------------------------------------
__global__ void k_bin(const float2* __restrict__ pos,
                      const float* __restrict__ rad,
                      const float* __restrict__ depth, int n) {
    int i = blockIdx.x * blockDim.x + threadIdx.x;
    if (i >= n) return;
    int a = blockIdx.y;

    float2 p = pos[i];
    float r = rad[i];
    int xmin, ymin, nx, ny;
    tile_range(p.x, p.y, r, xmin, ymin, nx, ny);
    if (a >= nx) return;

    float d = depth[i];
    int rep = depth_bucket(d) * 2 + (i & 1);
    unsigned int u = __float_as_uint(d);
    unsigned int desc = (u & 0x80000000u) ? u : ~(u | 0x80000000u);
    u64 key = ((u64)desc << 32) | (unsigned int)i;

    int rowbase = (xmin + a) * NBH + ymin;
    int rk[KWIN];
#pragma unroll
    for (int b = 0; b < KWIN; b++)
        if (b < ny)
            rk[b] = atomicAdd(&g_counts[(rowbase + b) * R + rep], 1);
#pragma unroll
    for (int b = 0; b < KWIN; b++)
        if (b < ny && rk[b] < SUBCAP)
            g_keys[(size_t)(rowbase + b) * CAP + rep * SUBCAP + rk[b]] = key;
}

// ---------------------------------------------------------------------------
// Pass 2: exclusive scan of 8160 tile totals (sum of 16 counters each).
// ---------------------------------------------------------------------------
__global__ void k_scan(float* __restrict__ out_count) {
    __shared__ int warp_pre[32];
    int t = threadIdx.x;
    int lane = t & 31, wid = t >> 5;
    int base = t * 8;
    int local[8];
    int s = 0;
#pragma unroll
    for (int j = 0; j < 8; j++) {
        int idx = base + j;
        int c = 0;
        if (idx < NB) {
            const int4* cp = reinterpret_cast<const int4*>(&g_counts[idx * R]);
#pragma unroll
            for (int q = 0; q < R / 4; q++) {
                int4 v = cp[q];
                c += v.x + v.y + v.z + v.w;
            }
        }
        local[j] = s;
        s += c;
    }
    int inc = s;
#pragma unroll
    for (int d = 1; d < 32; d <<= 1) {
        int v = __shfl_up_sync(0xffffffffu, inc, d);
        if (lane >= d) inc += v;
    }
    if (lane == 31) warp_pre[wid] = inc;
    __syncthreads();
    if (wid == 0) {
        int w = warp_pre[lane];
        int winc = w;
#pragma unroll
        for (int d = 1; d < 32; d <<= 1) {
            int v = __shfl_up_sync(0xffffffffu, winc, d);
            if (lane >= d) winc += v;
        }
        warp_pre[lane] = winc - w;
        if (lane == 31) g_total = winc;
    }
    __syncthreads();
    int pre = warp_pre[wid] + (inc - s);
#pragma unroll
    for (int j = 0; j < 8; j++) {
        int idx = base + j;
        if (idx < NB) {
            int off = pre + local[j];
            g_offsets[idx] = off;
            out_count[idx] = (float)off;
        }
    }
}

// ---------------------------------------------------------------------------
// Bitonic helpers
// ---------------------------------------------------------------------------
__device__ __forceinline__ u64 shfl_step(u64 v, int i, int j, int k) {
    u64 p = __shfl_xor_sync(0xffffffffu, v, j);
    bool lower = (i & j) == 0;
    bool up = (i & k) == 0;
    u64 mn = v < p ? v : p;
    u64 mx = v < p ? p : v;
    return (lower == up) ? mn : mx;
}

__device__ __forceinline__ void decode_store(u64 kk, float* idxr, float* depr, int pos) {
    unsigned int pid = (unsigned int)kk;
    unsigned int desc = (unsigned int)(kk >> 32);
    unsigned int u = (desc & 0x80000000u) ? desc : (~desc ^ 0x80000000u);
    idxr[pos] = (float)pid;
    depr[pos] = __uint_as_float(u);
}

// ---------------------------------------------------------------------------
// Fully warp-local bitonic sort of M = Q*32 elements from TWO replica
// sub-buckets (concatenated: unsorted input, order irrelevant pre-sort).
// Strides j<32 -> shuffles; j>=32 -> register exchanges. No smem/barriers.
// ---------------------------------------------------------------------------
template <int Q>
__device__ __forceinline__ void warp_sort_store(const u64* __restrict__ bp0,
                                                const u64* __restrict__ bp1,
                                                int c0, int n_b,
                                                float* __restrict__ idxr,
                                                float* __restrict__ depr,
                                                int outbase, int lane) {
    constexpr int M = Q * 32;
    u64 key[Q];
#pragma unroll
    for (int q = 0; q < Q; q++) {
        int idx = q * 32 + lane;
        u64 v = 0xFFFFFFFFFFFFFFFFull;
        if (idx < c0) v = bp0[idx];
        else if (idx < n_b) v = bp1[idx - c0];
        key[q] = v;
    }
#pragma unroll
    for (int k = 2; k <= M; k <<= 1) {
#pragma unroll
        for (int j = k >> 1; j > 0; j >>= 1) {
            if (j >= 32) {
                int qj = j >> 5;
#pragma unroll
                for (int q = 0; q < Q; q++) {
                    if (!(q & qj)) {
                        int qx = q | qj;
                        bool up = (((q * 32) & k) == 0);
                        u64 x = key[q], y = key[qx];
                        if ((x > y) == up) { key[q] = y; key[qx] = x; }
                    }
                }
            } else {
#pragma unroll
                for (int q = 0; q < Q; q++)
                    key[q] = shfl_step(key[q], q * 32 + lane, j, k);
            }
        }
    }
#pragma unroll
    for (int q = 0; q < Q; q++) {
        int idx = q * 32 + lane;
        if (idx < n_b) decode_store(key[q], idxr, depr, outbase + idx);
    }
}

// ---------------------------------------------------------------------------
// Pass 3: 8 warps per block; warp w sorts depth-octile w (both parity
// replicas) of its tile. Fused dead-tail fill. One block barrier.
// ---------------------------------------------------------------------------
__global__ void k_sort(float* __restrict__ idxr, float* __restrict__ depr, int E) {
    __shared__ int sh_cnt[R];
    int tile = blockIdx.x;
    int t = threadIdx.x;
    int lane = t & 31, w = t >> 5;

    if (t < R) {
        int c = g_counts[tile * R + t];
        sh_cnt[t] = min(c, SUBCAP);
    }

    // --- fused dead-tail fill [g_total, E) ---
    int total = g_total;
    int chunk = (E - total + NB - 1) / NB;
    int s0 = total + tile * chunk;
    int s1 = min(E, s0 + chunk);
    for (int i = s0 + t; i < s1; i += blockDim.x) {
        idxr[i] = -1.f;
        depr[i] = 0.f;
    }

    __syncthreads();
    if (t < R) g_counts[tile * R + t] = 0;   // reset for next graph replay

    int c0 = sh_cnt[2 * w];
    int c1 = sh_cnt[2 * w + 1];
    int n_b = c0 + c1;
    if (n_b <= 0) return;
    int boff = 0;
#pragma unroll
    for (int rr = 0; rr < R; rr++)
        if (rr < 2 * w) boff += sh_cnt[rr];
    int outbase = g_offsets[tile] + boff;
    const u64* bp0 = g_keys + (size_t)tile * CAP + (size_t)(2 * w) * SUBCAP;
    const u64* bp1 = bp0 + SUBCAP;

    if (n_b <= 32)       warp_sort_store<1>(bp0, bp1, c0, n_b, idxr, depr, outbase, lane);
    else if (n_b <= 64)  warp_sort_store<2>(bp0, bp1, c0, n_b, idxr, depr, outbase, lane);
    else if (n_b <= 128) warp_sort_store<4>(bp0, bp1, c0, n_b, idxr, depr, outbase, lane);
    else                 warp_sort_store<8>(bp0, bp1, c0, n_b, idxr, depr, outbase, lane);
}

// ---------------------------------------------------------------------------
extern "C" void kernel_launch(void* const* d_in, const int* in_sizes, int n_in,
                              void* d_out, int out_size) {
    const float2* pos = (const float2*)d_in[0];
    const float*  rad = (const float*)d_in[1];
    const float*  dep = (const float*)d_in[2];
    int n = in_sizes[1];
    float* out = (float*)d_out;
    int E = (out_size - NB) / 2;

    float* out_count = out;            // [NB]  exclusive tile offsets
    float* idxr      = out + NB;       // [E]   tile_indices
    float* depr      = out + NB + E;   // [E]   sorted_depth

    int nb_pts = (n + 255) / 256;
    dim3 bin_grid(nb_pts, KWIN);
    k_bin<<<bin_grid, 256>>>(pos, rad, dep, n);
    k_scan<<<1, 1024>>>(out_count);
    k_sort<<<NB, 256>>>(idxr, depr, E);
}

// round 12
// speedup vs baseline: 1.0172x; 1.0172x over previous
#include <cuda_runtime.h>
#include <stdint.h>

#define NBW 120
#define NBH 68
#define NB  8160
#define KWIN 5
#define R 8                       // depth-octile sub-buckets per tile
#define SUBCAP 160                // slots per sub-bucket (mean ~53, +14 sigma)
#define CAP (R * SUBCAP)          // 1280 slots per tile

typedef unsigned long long u64;
typedef unsigned int u32;

__device__ int g_counts[NB * R];   // zero-init; reset by k_sort each replay
__device__ int g_offsets[NB];
__device__ int g_total;
__device__ u32 g_ids[(size_t)NB * CAP];  // pid; slot = tile*CAP + bkt*SUBCAP + rank

// ---------------------------------------------------------------------------
// Tile range, identical clamping semantics to reference (exact: /16 == *0.0625)
// ---------------------------------------------------------------------------
__device__ __forceinline__ void tile_range(float x, float y, float r,
                                           int& xmin, int& ymin, int& nx, int& ny) {
    const float inv = 0.0625f;
    int x0 = (int)floorf((x - r) * inv);
    int y0 = (int)floorf((y - r) * inv);
    int x1 = (int)floorf((x + r) * inv) + 1;
    int y1 = (int)floorf((y + r) * inv) + 1;
    xmin = min(max(x0, 0), NBW);
    ymin = min(max(y0, 0), NBH);
    int xmax = min(max(x1, 0), NBW);
    int ymax = min(max(y1, 0), NBH);
    nx = min(xmax - xmin, KWIN);
    ny = min(ymax - ymin, KWIN);
}

// Depth octile: equal-mass N(0,1) buckets; larger depth -> lower bucket.
// Function of depth ONLY (ties share a bucket); monotone non-increasing in
// depth -> concatenating sorted buckets in order is a full sort.
__device__ __forceinline__ int depth_bucket(float d) {
    int b = 0;
    b += d < 1.1503494f;
    b += d < 0.6744898f;
    b += d < 0.3186394f;
    b += d < 0.0f;
    b += d < -0.3186394f;
    b += d < -0.6744898f;
    b += d < -1.1503494f;
    return b;
}

// ---------------------------------------------------------------------------
// Pass 1: fused count+scatter into (tile, depth-octile) sub-buckets.
// Entries are 4-byte pids; scratch is fully L2-resident (42MB).
// ---------------------------------------------------------------------------
__global__ void k_bin(const float2* __restrict__ pos,
                      const float* __restrict__ rad,
                      const float* __restrict__ depth, int n) {
    int i = blockIdx.x * blockDim.x + threadIdx.x;
    if (i >= n) return;
    float2 p = pos[i];
    float r = rad[i];
    int rep = depth_bucket(depth[i]);

    int xmin, ymin, nx, ny;
    tile_range(p.x, p.y, r, xmin, ymin, nx, ny);
    int tbase = xmin * NBH + ymin;

    int rk[KWIN * KWIN];
#pragma unroll
    for (int a = 0; a < KWIN; a++) {
#pragma unroll
        for (int b = 0; b < KWIN; b++) {
            int e = a * KWIN + b;
            if (a < nx && b < ny)
                rk[e] = atomicAdd(&g_counts[(tbase + a * NBH + b) * R + rep], 1);
        }
    }
#pragma unroll
    for (int a = 0; a < KWIN; a++) {
#pragma unroll
        for (int b = 0; b < KWIN; b++) {
            int e = a * KWIN + b;
            if (a < nx && b < ny && rk[e] < SUBCAP) {
                size_t slot = (size_t)(tbase + a * NBH + b) * CAP
                            + rep * SUBCAP + rk[e];
                g_ids[slot] = (u32)i;
            }
        }
    }
}

// ---------------------------------------------------------------------------
// Pass 2: exclusive scan of 8160 tile totals (sum of 8 sub-buckets each).
// ---------------------------------------------------------------------------
__global__ void k_scan(float* __restrict__ out_count) {
    __shared__ int warp_pre[32];
    int t = threadIdx.x;
    int lane = t & 31, wid = t >> 5;
    int base = t * 8;
    int local[8];
    int s = 0;
#pragma unroll
    for (int j = 0; j < 8; j++) {
        int idx = base + j;
        int c = 0;
        if (idx < NB) {
            const int4* cp = reinterpret_cast<const int4*>(&g_counts[idx * R]);
            int4 c0 = cp[0], c1 = cp[1];
            c = c0.x + c0.y + c0.z + c0.w + c1.x + c1.y + c1.z + c1.w;
        }
        local[j] = s;
        s += c;
    }
    int inc = s;
#pragma unroll
    for (int d = 1; d < 32; d <<= 1) {
        int v = __shfl_up_sync(0xffffffffu, inc, d);
        if (lane >= d) inc += v;
    }
    if (lane == 31) warp_pre[wid] = inc;
    __syncthreads();
    if (wid == 0) {
        int w = warp_pre[lane];
        int winc = w;
#pragma unroll
        for (int d = 1; d < 32; d <<= 1) {
            int v = __shfl_up_sync(0xffffffffu, winc, d);
            if (lane >= d) winc += v;
        }
        warp_pre[lane] = winc - w;
        if (lane == 31) g_total = winc;
    }
    __syncthreads();
    int pre = warp_pre[wid] + (inc - s);
#pragma unroll
    for (int j = 0; j < 8; j++) {
        int idx = base + j;
        if (idx < NB) {
            int off = pre + local[j];
            g_offsets[idx] = off;
            out_count[idx] = (float)off;
        }
    }
}

// ---------------------------------------------------------------------------
// Bitonic helpers
// ---------------------------------------------------------------------------
__device__ __forceinline__ u64 shfl_step(u64 v, int i, int j, int k) {
    u64 p = __shfl_xor_sync(0xffffffffu, v, j);
    bool lower = (i & j) == 0;
    bool up = (i & k) == 0;
    u64 mn = v < p ? v : p;
    u64 mx = v < p ? p : v;
    return (lower == up) ? mn : mx;
}

__device__ __forceinline__ void decode_store(u64 kk, float* idxr, float* depr, int pos) {
    unsigned int pid = (unsigned int)kk;
    unsigned int desc = (unsigned int)(kk >> 32);
    unsigned int u = (desc & 0x80000000u) ? desc : (~desc ^ 0x80000000u);
    idxr[pos] = (float)pid;
    depr[pos] = __uint_as_float(u);
}

// ---------------------------------------------------------------------------
// Fully warp-local bitonic sort of M = Q*32 elements: load pid, gather depth
// (L2-resident), rebuild exact u64 key, sort in registers, store output.
// Strides j<32 -> shuffles; j>=32 -> register exchanges. No smem/barriers.
// ---------------------------------------------------------------------------
template <int Q>
__device__ __forceinline__ void warp_sort_store(const u32* __restrict__ bp, int n_b,
                                                const float* __restrict__ depth,
                                                float* __restrict__ idxr,
                                                float* __restrict__ depr,
                                                int outbase, int lane) {
    constexpr int M = Q * 32;
    u64 key[Q];
#pragma unroll
    for (int q = 0; q < Q; q++) {
        int idx = q * 32 + lane;
        u64 v = 0xFFFFFFFFFFFFFFFFull;
        if (idx < n_b) {
            u32 pid = bp[idx];
            unsigned int u = __float_as_uint(depth[pid]);
            unsigned int desc = (u & 0x80000000u) ? u : ~(u | 0x80000000u);
            v = ((u64)desc << 32) | pid;
        }
        key[q] = v;
    }
#pragma unroll
    for (int k = 2; k <= M; k <<= 1) {
#pragma unroll
        for (int j = k >> 1; j > 0; j >>= 1) {
            if (j >= 32) {
                int qj = j >> 5;
#pragma unroll
                for (int q = 0; q < Q; q++) {
                    if (!(q & qj)) {
                        int qx = q | qj;
                        bool up = (((q * 32) & k) == 0);
                        u64 x = key[q], y = key[qx];
                        if ((x > y) == up) { key[q] = y; key[qx] = x; }
                    }
                }
            } else {
#pragma unroll
                for (int q = 0; q < Q; q++)
                    key[q] = shfl_step(key[q], q * 32 + lane, j, k);
            }
        }
    }
#pragma unroll
    for (int q = 0; q < Q; q++) {
        int idx = q * 32 + lane;
        if (idx < n_b) decode_store(key[q], idxr, depr, outbase + idx);
    }
}

// ---------------------------------------------------------------------------
// Pass 3: 8 warps per block, warp w sorts depth-octile bucket w of its tile.
// Fused vectorized dead-tail fill. One block barrier.
// ---------------------------------------------------------------------------
__global__ void k_sort(const float* __restrict__ depth,
                       float* __restrict__ idxr, float* __restrict__ depr, int E) {
    __shared__ int sh_cnt[R];
    int tile = blockIdx.x;
    int t = threadIdx.x;
    int lane = t & 31, w = t >> 5;

    if (t < R) {
        int c = g_counts[tile * R + t];
        sh_cnt[t] = min(c, SUBCAP);
    }

    // --- fused dead-tail fill [g_total, E), float4 where aligned ---
    {
        int total = g_total;
        int chunk = ((E - total + NB - 1) / NB + 3) & ~3;   // 4-aligned chunk
        int s0 = total + tile * chunk;
        int s1 = min(E, s0 + chunk);
        if (s1 > s0) {
            if (s1 - s0 < 8) {
                for (int i = s0 + t; i < s1; i += blockDim.x) {
                    idxr[i] = -1.f;
                    depr[i] = 0.f;
                }
            } else {
                int a0 = (s0 + 3) & ~3;
                int a1 = s1 & ~3;
                if (s0 + t < a0) { idxr[s0 + t] = -1.f; depr[s0 + t] = 0.f; }
                float4 m1 = make_float4(-1.f, -1.f, -1.f, -1.f);
                float4 z0 = make_float4(0.f, 0.f, 0.f, 0.f);
                float4* i4 = reinterpret_cast<float4*>(idxr);
                float4* d4 = reinterpret_cast<float4*>(depr);
                for (int i = (a0 >> 2) + t; i < (a1 >> 2); i += blockDim.x) {
                    i4[i] = m1;
                    d4[i] = z0;
                }
                if (a1 + t < s1) { idxr[a1 + t] = -1.f; depr[a1 + t] = 0.f; }
            }
        }
    }

    __syncthreads();
    if (t < R) g_counts[tile * R + t] = 0;   // reset for next graph replay

    int n_b = sh_cnt[w];
    if (n_b <= 0) return;
    int boff = 0;
#pragma unroll
    for (int rr = 0; rr < R; rr++)
        if (rr < w) boff += sh_cnt[rr];
    int outbase = g_offsets[tile] + boff;
    const u32* bp = g_ids + (size_t)tile * CAP + (size_t)w * SUBCAP;

    if (n_b <= 32)       warp_sort_store<1>(bp, n_b, depth, idxr, depr, outbase, lane);
    else if (n_b <= 64)  warp_sort_store<2>(bp, n_b, depth, idxr, depr, outbase, lane);
    else if (n_b <= 128) warp_sort_store<4>(bp, n_b, depth, idxr, depr, outbase, lane);
    else                 warp_sort_store<8>(bp, n_b, depth, idxr, depr, outbase, lane);
}

// ---------------------------------------------------------------------------
extern "C" void kernel_launch(void* const* d_in, const int* in_sizes, int n_in,
                              void* d_out, int out_size) {
    const float2* pos = (const float2*)d_in[0];
    const float*  rad = (const float*)d_in[1];
    const float*  dep = (const float*)d_in[2];
    int n = in_sizes[1];
    float* out = (float*)d_out;
    int E = (out_size - NB) / 2;

    float* out_count = out;            // [NB]  exclusive tile offsets
    float* idxr      = out + NB;       // [E]   tile_indices
    float* depr      = out + NB + E;   // [E]   sorted_depth

    int nb_pts = (n + 255) / 256;
    k_bin<<<nb_pts, 256>>>(pos, rad, dep, n);
    k_scan<<<1, 1024>>>(out_count);
    k_sort<<<NB, 256>>>(dep, idxr, depr, E);
}

// round 13
// speedup vs baseline: 1.0595x; 1.0415x over previous
#include <cuda_runtime.h>
#include <stdint.h>

#define NBW 120
#define NBH 68
#define NB  8160
#define KWIN 5
#define R 8                       // depth-octile sub-buckets per tile
#define CSTRIDE 32                // counter ints per tile (128B line padding)
#define SUBCAP 192                // slots per sub-bucket (mean ~53, +19 sigma)
#define CAP (R * SUBCAP)          // 1536 slots per tile

typedef unsigned long long u64;

__device__ int g_counts[NB * CSTRIDE]; // zero-init; reset by k_sort each replay
__device__ int g_offsets[NB];
__device__ int g_total;
__device__ u64 g_keys[(size_t)NB * CAP];  // slot = tile*CAP + bkt*SUBCAP + rank

// ---------------------------------------------------------------------------
// Tile range, identical clamping semantics to reference (exact: /16 == *0.0625)
// ---------------------------------------------------------------------------
__device__ __forceinline__ void tile_range(float x, float y, float r,
                                           int& xmin, int& ymin, int& nx, int& ny) {
    const float inv = 0.0625f;
    int x0 = (int)floorf((x - r) * inv);
    int y0 = (int)floorf((y - r) * inv);
    int x1 = (int)floorf((x + r) * inv) + 1;
    int y1 = (int)floorf((y + r) * inv) + 1;
    xmin = min(max(x0, 0), NBW);
    ymin = min(max(y0, 0), NBH);
    int xmax = min(max(x1, 0), NBW);
    int ymax = min(max(y1, 0), NBH);
    nx = min(xmax - xmin, KWIN);
    ny = min(ymax - ymin, KWIN);
}

// Depth octile: equal-mass N(0,1) buckets; larger depth -> lower bucket.
// Function of depth ONLY (ties share a bucket); monotone non-increasing in
// depth -> concatenating sorted buckets in order is a full sort.
__device__ __forceinline__ int depth_bucket(float d) {
    int b = 0;
    b += d < 1.1503494f;
    b += d < 0.6744898f;
    b += d < 0.3186394f;
    b += d < 0.0f;
    b += d < -0.3186394f;
    b += d < -0.6744898f;
    b += d < -1.1503494f;
    return b;
}

// ---------------------------------------------------------------------------
// Pass 1: fused count+scatter into (tile, depth-octile) sub-buckets.
// Counters padded to one 128B line per tile -> line-parallel L2 atomics.
// ---------------------------------------------------------------------------
__global__ void k_bin(const float2* __restrict__ pos,
                      const float* __restrict__ rad,
                      const float* __restrict__ depth, int n) {
    int i = blockIdx.x * blockDim.x + threadIdx.x;
    if (i >= n) return;
    float2 p = pos[i];
    float r = rad[i];
    float d = depth[i];
    int rep = depth_bucket(d);
    unsigned int u = __float_as_uint(d);
    unsigned int desc = (u & 0x80000000u) ? u : ~(u | 0x80000000u);
    u64 key = ((u64)desc << 32) | (unsigned int)i;

    int xmin, ymin, nx, ny;
    tile_range(p.x, p.y, r, xmin, ymin, nx, ny);
    for (int a = 0; a < nx; a++) {
        int rowbase = (xmin + a) * NBH + ymin;
        for (int b = 0; b < ny; b++) {
            int t = rowbase + b;
            int rk = atomicAdd(&g_counts[t * CSTRIDE + rep], 1);
            if (rk < SUBCAP)
                g_keys[(size_t)t * CAP + rep * SUBCAP + rk] = key;
        }
    }
}

// ---------------------------------------------------------------------------
// Pass 2: exclusive scan of 8160 tile totals (sum of 8 sub-buckets each).
// ---------------------------------------------------------------------------
__global__ void k_scan(float* __restrict__ out_count) {
    __shared__ int warp_pre[32];
    int t = threadIdx.x;
    int lane = t & 31, wid = t >> 5;
    int base = t * 8;
    int local[8];
    int s = 0;
#pragma unroll
    for (int j = 0; j < 8; j++) {
        int idx = base + j;
        int c = 0;
        if (idx < NB) {
            const int4* cp = reinterpret_cast<const int4*>(&g_counts[idx * CSTRIDE]);
            int4 c0 = cp[0], c1 = cp[1];
            c = c0.x + c0.y + c0.z + c0.w + c1.x + c1.y + c1.z + c1.w;
        }
        local[j] = s;
        s += c;
    }
    int inc = s;
#pragma unroll
    for (int d = 1; d < 32; d <<= 1) {
        int v = __shfl_up_sync(0xffffffffu, inc, d);
        if (lane >= d) inc += v;
    }
    if (lane == 31) warp_pre[wid] = inc;
    __syncthreads();
    if (wid == 0) {
        int w = warp_pre[lane];
        int winc = w;
#pragma unroll
        for (int d = 1; d < 32; d <<= 1) {
            int v = __shfl_up_sync(0xffffffffu, winc, d);
            if (lane >= d) winc += v;
        }
        warp_pre[lane] = winc - w;
        if (lane == 31) g_total = winc;
    }
    __syncthreads();
    int pre = warp_pre[wid] + (inc - s);
#pragma unroll
    for (int j = 0; j < 8; j++) {
        int idx = base + j;
        if (idx < NB) {
            int off = pre + local[j];
            g_offsets[idx] = off;
            out_count[idx] = (float)off;
        }
    }
}

// ---------------------------------------------------------------------------
// Bitonic helpers
// ---------------------------------------------------------------------------
__device__ __forceinline__ u64 shfl_step(u64 v, int i, int j, int k) {
    u64 p = __shfl_xor_sync(0xffffffffu, v, j);
    bool lower = (i & j) == 0;
    bool up = (i & k) == 0;
    u64 mn = v < p ? v : p;
    u64 mx = v < p ? p : v;
    return (lower == up) ? mn : mx;
}

__device__ __forceinline__ void decode_store(u64 kk, float* idxr, float* depr, int pos) {
    unsigned int pid = (unsigned int)kk;
    unsigned int desc = (unsigned int)(kk >> 32);
    unsigned int u = (desc & 0x80000000u) ? desc : (~desc ^ 0x80000000u);
    idxr[pos] = (float)pid;
    depr[pos] = __uint_as_float(u);
}

// ---------------------------------------------------------------------------
// Fully warp-local bitonic sort of M = Q*32 elements, 64-bit keys.
// Strides j<32 -> shuffles; j>=32 -> register exchanges. No smem/barriers.
// ---------------------------------------------------------------------------
template <int Q>
__device__ __forceinline__ void warp_sort_store(const u64* __restrict__ bp, int n_b,
                                                float* __restrict__ idxr,
                                                float* __restrict__ depr,
                                                int outbase, int lane) {
    constexpr int M = Q * 32;
    u64 key[Q];
#pragma unroll
    for (int q = 0; q < Q; q++) {
        int idx = q * 32 + lane;
        key[q] = (idx < n_b) ? bp[idx] : 0xFFFFFFFFFFFFFFFFull;
    }
#pragma unroll
    for (int k = 2; k <= M; k <<= 1) {
#pragma unroll
        for (int j = k >> 1; j > 0; j >>= 1) {
            if (j >= 32) {
                int qj = j >> 5;
#pragma unroll
                for (int q = 0; q < Q; q++) {
                    if (!(q & qj)) {
                        int qx = q | qj;
                        bool up = (((q * 32) & k) == 0);
                        u64 x = key[q], y = key[qx];
                        if ((x > y) == up) { key[q] = y; key[qx] = x; }
                    }
                }
            } else {
#pragma unroll
                for (int q = 0; q < Q; q++)
                    key[q] = shfl_step(key[q], q * 32 + lane, j, k);
            }
        }
    }
#pragma unroll
    for (int q = 0; q < Q; q++) {
        int idx = q * 32 + lane;
        if (idx < n_b) decode_store(key[q], idxr, depr, outbase + idx);
    }
}

// ---------------------------------------------------------------------------
// Pass 3: 8 warps per block, warp w sorts depth-octile bucket w of its tile.
// Fused vectorized dead-tail fill. One block barrier.
// ---------------------------------------------------------------------------
__global__ void k_sort(float* __restrict__ idxr, float* __restrict__ depr, int E) {
    __shared__ int sh_cnt[R];
    int tile = blockIdx.x;
    int t = threadIdx.x;
    int lane = t & 31, w = t >> 5;

    if (t < R) {
        int c = g_counts[tile * CSTRIDE + t];
        sh_cnt[t] = min(c, SUBCAP);
    }

    // --- fused dead-tail fill [g_total, E), float4 where aligned ---
    {
        int total = g_total;
        int chunk = ((E - total + NB - 1) / NB + 3) & ~3;   // 4-aligned chunk
        int s0 = total + tile * chunk;
        int s1 = min(E, s0 + chunk);
        if (s1 > s0) {
            if (s1 - s0 < 8) {
                for (int i = s0 + t; i < s1; i += blockDim.x) {
                    idxr[i] = -1.f;
                    depr[i] = 0.f;
                }
            } else {
                int a0 = (s0 + 3) & ~3;
                int a1 = s1 & ~3;
                if (s0 + t < a0) { idxr[s0 + t] = -1.f; depr[s0 + t] = 0.f; }
                float4 m1 = make_float4(-1.f, -1.f, -1.f, -1.f);
                float4 z0 = make_float4(0.f, 0.f, 0.f, 0.f);
                float4* i4 = reinterpret_cast<float4*>(idxr);
                float4* d4 = reinterpret_cast<float4*>(depr);
                for (int i = (a0 >> 2) + t; i < (a1 >> 2); i += blockDim.x) {
                    i4[i] = m1;
                    d4[i] = z0;
                }
                if (a1 + t < s1) { idxr[a1 + t] = -1.f; depr[a1 + t] = 0.f; }
            }
        }
    }

    __syncthreads();
    if (t < R) g_counts[tile * CSTRIDE + t] = 0;   // reset for next replay

    int n_b = sh_cnt[w];
    if (n_b <= 0) return;
    int boff = 0;
#pragma unroll
    for (int rr = 0; rr < R; rr++)
        if (rr < w) boff += sh_cnt[rr];
    int outbase = g_offsets[tile] + boff;
    const u64* bp = g_keys + (size_t)tile * CAP + (size_t)w * SUBCAP;

    if (n_b <= 32)       warp_sort_store<1>(bp, n_b, idxr, depr, outbase, lane);
    else if (n_b <= 64)  warp_sort_store<2>(bp, n_b, idxr, depr, outbase, lane);
    else if (n_b <= 128) warp_sort_store<4>(bp, n_b, idxr, depr, outbase, lane);
    else                 warp_sort_store<8>(bp, n_b, idxr, depr, outbase, lane);
}

// ---------------------------------------------------------------------------
extern "C" void kernel_launch(void* const* d_in, const int* in_sizes, int n_in,
                              void* d_out, int out_size) {
    const float2* pos = (const float2*)d_in[0];
    const float*  rad = (const float*)d_in[1];
    const float*  dep = (const float*)d_in[2];
    int n = in_sizes[1];
    float* out = (float*)d_out;
    int E = (out_size - NB) / 2;

    float* out_count = out;            // [NB]  exclusive tile offsets
    float* idxr      = out + NB;       // [E]   tile_indices
    float* depr      = out + NB + E;   // [E]   sorted_depth

    int nb_pts = (n + 255) / 256;
    k_bin<<<nb_pts, 256>>>(pos, rad, dep, n);
    k_scan<<<1, 1024>>>(out_count);
    k_sort<<<NB, 256>>>(idxr, depr, E);
}